// round 16
// baseline (speedup 1.0000x reference)
#include <cuda_runtime.h>
#include <cuda_fp16.h>
#include <cstdint>

#define B_B 4096
#define HEADS_ 8
#define NW_ 64
#define Q_SCALE 0.17677669529663687f
#define M_ROWS (B_B * 49)              // 200704 = 1568 * 128

// ---------------- scratch ----------------
__device__ __align__(16) __half g_xbuf[(size_t)M_ROWS * 768];  // k|v|q fp16
__device__ __align__(16) __half g_ybuf[(size_t)M_ROWS * 768];
__device__ __align__(16) __half g_ox  [(size_t)M_ROWS * 256];
__device__ __align__(16) __half g_oy  [(size_t)M_ROWS * 256];
__device__ __align__(16) __half g_wx  [768 * 256];  // W^T [n][k] fp16
__device__ __align__(16) __half g_wy  [768 * 256];
__device__ __align__(16) __half g_pw  [256 * 256];
__device__ __align__(16) __half g_py  [256 * 256];
__device__ __align__(16) float  g_bx  [768];
__device__ __align__(16) float  g_by  [768];
__device__ __align__(16) float  g_rpbH[HEADS_ * 2452 + 64];    // +64 OOB pad

// ---------------- helpers ----------------
__device__ __forceinline__ uint32_t smem_u32(const void* p) {
    uint32_t a;
    asm("{ .reg .u64 t; cvta.to.shared.u64 t, %1; cvt.u32.u64 %0, t; }" : "=r"(a) : "l"(p));
    return a;
}
__device__ __forceinline__ unsigned packh2(float a, float b) {
    __half2 h = __floats2half2_rn(a, b);
    return *(unsigned*)&h;
}
__device__ __forceinline__ void mma_f16(float* c, const unsigned* a, const unsigned* b) {
    asm volatile(
        "mma.sync.aligned.m16n8k16.row.col.f32.f16.f16.f32 "
        "{%0,%1,%2,%3}, {%4,%5,%6,%7}, {%8,%9}, {%0,%1,%2,%3};\n"
        : "+f"(c[0]), "+f"(c[1]), "+f"(c[2]), "+f"(c[3])
        : "r"(a[0]), "r"(a[1]), "r"(a[2]), "r"(a[3]), "r"(b[0]), "r"(b[1]));
}
__device__ __forceinline__ void ldm_x4(unsigned* r, uint32_t addr) {
    asm volatile("ldmatrix.sync.aligned.m8n8.x4.shared.b16 {%0,%1,%2,%3}, [%4];"
        : "=r"(r[0]), "=r"(r[1]), "=r"(r[2]), "=r"(r[3]) : "r"(addr));
}
__device__ __forceinline__ void cpasync16(uint32_t dst, const void* src) {
    asm volatile("cp.async.cg.shared.global [%0], [%1], 16;" :: "r"(dst), "l"(src));
}
#define CP_COMMIT() asm volatile("cp.async.commit_group;" ::: "memory")

// ---------------- prep: single kernel ----------------
__global__ void prep_all(
    const float* __restrict__ qkv_w,   const float* __restrict__ qkv_b,
    const float* __restrict__ qxw,     const float* __restrict__ qxb,
    const float* __restrict__ qkv_y_w, const float* __restrict__ qkv_y_b,
    const float* __restrict__ qyw,     const float* __restrict__ qyb,
    const float* __restrict__ proj_w,  const float* __restrict__ proj_y_w,
    const float* __restrict__ rpbt,    const int* __restrict__ rpi,
    __half* __restrict__ wx, float* __restrict__ bxv,
    __half* __restrict__ wy, float* __restrict__ byv,
    __half* __restrict__ pw, __half* __restrict__ py,
    float* __restrict__ rpbH)
{
    int i = blockIdx.x * 256 + threadIdx.x;
    if (i < 768 * 256) {
        int n = i >> 8, k = i & 255;
        float vx = (n < 512) ? qkv_w[k * 512 + n]   : qxw[k * 256 + (n - 512)] * Q_SCALE;
        float vy = (n < 512) ? qkv_y_w[k * 512 + n] : qyw[k * 256 + (n - 512)] * Q_SCALE;
        wx[i] = __float2half_rn(vx);
        wy[i] = __float2half_rn(vy);
    }
    if (i < 768) {
        bxv[i] = (i < 512) ? qkv_b[i]   : qxb[i - 512] * Q_SCALE;
        byv[i] = (i < 512) ? qkv_y_b[i] : qyb[i - 512] * Q_SCALE;
    }
    if (i < 65536) {
        int n = i >> 8, k = i & 255;
        pw[i] = __float2half_rn(proj_w[k * 256 + n]);
        py[i] = __float2half_rn(proj_y_w[k * 256 + n]);
    }
    if (i < HEADS_ * 2401) {
        int h = i / 2401, ij = i % 2401;
        int r = ij / 49, j = ij % 49;
        rpbH[h * 2452 + r * 50 + j] = rpbt[rpi[ij] * 8 + h];
    }
}

// ---------------- fp16 mma GEMM w/ ldmatrix + staged epilogue ----------------
#define GH_AS0  0
#define GH_AS1  2560
#define GH_BS0  5120
#define GH_BS1  7680
#define GEMM_SMEM_BYTES (10240 * 4)

template<int AFP16>
__global__ __launch_bounds__(128) void gemm_h(
    const void* __restrict__ A0v, const __half* __restrict__ W0,
    const float* __restrict__ b0, void* __restrict__ C0v,
    const void* __restrict__ A1v, const __half* __restrict__ W1,
    const float* __restrict__ b1, void* __restrict__ C1v, int Ncol)
{
    extern __shared__ unsigned smg[];
    const uint32_t sb = smem_u32(smg);

    const void*  Av   = blockIdx.z ? A1v : A0v;
    const __half* W   = blockIdx.z ? W1 : W0;
    const float* bias = blockIdx.z ? b1 : b0;
    void*        Cv   = blockIdx.z ? C1v : C0v;

    const int t = threadIdx.x;
    const int warpId = t >> 5, lane = t & 31;
    const int gid = lane >> 2, tid4 = lane & 3;
    const int wm = (warpId & 1) * 64;
    const int wn = (warpId >> 1) * 64;
    const size_t tileM = (size_t)blockIdx.y * 128;
    const int tileN = blockIdx.x * 128;

    const int mi = lane >> 3, li = lane & 7;
    uint32_t aRel[4], bRel[4];
#pragma unroll
    for (int mt = 0; mt < 4; mt++)
        aRel[mt] = (uint32_t)(((wm + mt * 16 + (mi & 1) * 8 + li) * 20 + (mi >> 1) * 4) * 4);
#pragma unroll
    for (int np = 0; np < 4; np++)
        bRel[np] = (uint32_t)(((wn + (2 * np + (mi >> 1)) * 8 + li) * 20 + (mi & 1) * 4) * 4);

    float acc[4][8][4];
#pragma unroll
    for (int i = 0; i < 4; i++)
#pragma unroll
        for (int j = 0; j < 8; j++)
#pragma unroll
            for (int l = 0; l < 4; l++) acc[i][j][l] = 0.f;

#define GH_BFILL(stage, ch) do {                                                     \
    uint32_t bs_ = sb + ((stage) ? GH_BS1 : GH_BS0) * 4;                             \
    const __half* wsrc_ = W + (size_t)(tileN + t) * 256 + (ch) * 32;                 \
    _Pragma("unroll")                                                                \
    for (int cc = 0; cc < 4; cc++)                                                   \
        cpasync16(bs_ + (uint32_t)((t * 20 + cc * 4) * 4), wsrc_ + cc * 8);          \
} while (0)
#define GH_AFILL16(stage, ch) do {                                                   \
    uint32_t as_ = sb + ((stage) ? GH_AS1 : GH_AS0) * 4;                             \
    const __half* asrc_ = (const __half*)Av + (tileM + t) * 256 + (ch) * 32;         \
    _Pragma("unroll")                                                                \
    for (int cc = 0; cc < 4; cc++)                                                   \
        cpasync16(as_ + (uint32_t)((t * 20 + cc * 4) * 4), asrc_ + cc * 8);          \
} while (0)

    const int arow0 = t >> 3, aq = t & 7;
    const float* Af = (const float*)Av;
    float4 pa[8];

    if (AFP16) {
        GH_AFILL16(0, 0); GH_BFILL(0, 0); CP_COMMIT();
        GH_AFILL16(1, 1); GH_BFILL(1, 1); CP_COMMIT();
    } else {
#pragma unroll
        for (int i = 0; i < 8; i++)
            pa[i] = *(const float4*)(Af + (tileM + arow0 + i * 16) * 256 + aq * 4);
        GH_BFILL(0, 0); CP_COMMIT();
        GH_BFILL(1, 1); CP_COMMIT();
    }

    for (int c = 0; c < 8; c++) {
        const int s = c & 1;
        unsigned* As = smg + (s ? GH_AS1 : GH_AS0);
        const uint32_t aBase = sb + (s ? GH_AS1 : GH_AS0) * 4;
        const uint32_t bBase = sb + (s ? GH_BS1 : GH_BS0) * 4;

        if (!AFP16) {
#pragma unroll
            for (int i = 0; i < 8; i++) {
                uint2 u = { packh2(pa[i].x, pa[i].y), packh2(pa[i].z, pa[i].w) };
                *(uint2*)&As[(arow0 + i * 16) * 20 + aq * 2] = u;
            }
        }
        if (c < 7) asm volatile("cp.async.wait_group 1;" ::: "memory");
        else       asm volatile("cp.async.wait_group 0;" ::: "memory");
        __syncthreads();

        if (!AFP16 && c < 7) {
#pragma unroll
            for (int i = 0; i < 8; i++)
                pa[i] = *(const float4*)(Af + (tileM + arow0 + i * 16) * 256
                                         + (c + 1) * 32 + aq * 4);
        }

#pragma unroll
        for (int ks = 0; ks < 2; ks++) {
            unsigned a[4][4];
#pragma unroll
            for (int mt = 0; mt < 4; mt++)
                ldm_x4(a[mt], aBase + aRel[mt] + ks * 32);
            unsigned bf[4][4];
#pragma unroll
            for (int np = 0; np < 4; np++)
                ldm_x4(bf[np], bBase + bRel[np] + ks * 32);
#pragma unroll
            for (int nt = 0; nt < 8; nt++) {
                unsigned b2[2] = { bf[nt >> 1][(nt & 1) * 2], bf[nt >> 1][(nt & 1) * 2 + 1] };
#pragma unroll
                for (int mt = 0; mt < 4; mt++)
                    mma_f16(acc[mt][nt], a[mt], b2);
            }
        }
        __syncthreads();

        if (c < 6) {
            if (AFP16) GH_AFILL16(s, c + 2);
            GH_BFILL(s, c + 2);
            CP_COMMIT();
        }
    }

    // ---------------- staged epilogue (smem reused, coalesced stores) --------
    if (AFP16) {
        // fp32 C: two passes of 64 rows through float Fs[64][132]
        float* Fs = (float*)smg;
        float* C = (float*)Cv;
#pragma unroll
        for (int p = 0; p < 2; p++) {
            if ((wm >> 6) == p) {
#pragma unroll
                for (int mt = 0; mt < 4; mt++) {
                    int rl = mt * 16 + gid;
#pragma unroll
                    for (int nt = 0; nt < 8; nt++) {
                        int col = wn + nt * 8 + tid4 * 2;
                        float bb0 = bias[tileN + col], bb1 = bias[tileN + col + 1];
                        float2 v0 = { acc[mt][nt][0] + bb0, acc[mt][nt][1] + bb1 };
                        float2 v1 = { acc[mt][nt][2] + bb0, acc[mt][nt][3] + bb1 };
                        *(float2*)&Fs[rl * 132 + col] = v0;
                        *(float2*)&Fs[(rl + 8) * 132 + col] = v1;
                    }
                }
            }
            __syncthreads();
#pragma unroll
            for (int i = 0; i < 16; i++) {
                int u = t + i * 128;            // 0..2047
                int row = u >> 5, q = (u & 31) * 4;
                float4 v = *(float4*)&Fs[row * 132 + q];
                *(float4*)&C[(tileM + p * 64 + row) * Ncol + tileN + q] = v;
            }
            __syncthreads();
        }
    } else {
        // fp16 C: single pass through unsigned Cs[128][65]
        unsigned* Cs = smg;
        __half* C = (__half*)Cv;
#pragma unroll
        for (int mt = 0; mt < 4; mt++) {
            int rl = wm + mt * 16 + gid;
#pragma unroll
            for (int nt = 0; nt < 8; nt++) {
                int col = wn + nt * 8 + tid4 * 2;
                float bb0 = bias[tileN + col], bb1 = bias[tileN + col + 1];
                int colu = (col >> 1);
                Cs[rl * 65 + colu] = packh2(acc[mt][nt][0] + bb0, acc[mt][nt][1] + bb1);
                Cs[(rl + 8) * 65 + colu] = packh2(acc[mt][nt][2] + bb0, acc[mt][nt][3] + bb1);
            }
        }
        __syncthreads();
#pragma unroll
        for (int i = 0; i < 16; i++) {
            int u = t + i * 128;                // 0..2047
            int row = u >> 4, cu = (u & 15) * 4;
            uint4 v = { Cs[row * 65 + cu], Cs[row * 65 + cu + 1],
                        Cs[row * 65 + cu + 2], Cs[row * 65 + cu + 3] };
            *(uint4*)&C[(tileM + row) * Ncol + tileN + cu * 2] = v;
        }
    }
}

// ---------------- attention v4 (unchanged from R15) ----------------
#define AT_ST0  0
#define AT_ST1  5120
#define AT_VT   10240
#define AT_BASE 12544
#define AT_TOT  (AT_BASE + 2452 + 64)
#define ATTN_SMEM_BYTES (AT_TOT * 4)     // 60,240 B

__device__ __forceinline__ void fill_qk_g(uint32_t sb, int stw, int g,
    const __half* Qp, const __half* Kp, int h, int tl)
{
    for (int u = tl; u < 392; u += 128) {
        int qk = u / 196, rem = u - qk * 196;
        int row = rem >> 2, cc = rem & 3;
        const __half* src = (qk ? Kp : Qp) + (size_t)h * 32 + row * 768 + cc * 8;
        uint32_t dstw = (uint32_t)(stw + g * 2560 + qk * 1280 + row * 20 + cc * 4);
        cpasync16(sb + dstw * 4, src);
    }
}

__global__ __launch_bounds__(256) void attn_kernel(
    const float* __restrict__ nuc, const float* __restrict__ mask,
    const float* __restrict__ rpbH)
{
    extern __shared__ unsigned smw[];
    const uint32_t sb = smem_u32(smw);
    float* base = (float*)(smw + AT_BASE);

    const int b = blockIdx.x;
    const __half* Q0 = g_ybuf + 512 + (size_t)b * 49 * 768;
    const __half* K0 = g_xbuf + (size_t)b * 49 * 768;
    const __half* Q1 = g_xbuf + 512 + (size_t)b * 49 * 768;
    const __half* K1 = g_ybuf + (size_t)b * 49 * 768;

    const int t = threadIdx.x;
    const int w = t >> 5, lane = t & 31;
    const int gid = lane >> 2, tid4 = lane & 3;
    const int g = w >> 2;
    const int R = (w & 3) * 16;
    const int tl = t & 127;
    const int wi = b & (NW_ - 1);
    const float* nb = nuc + (size_t)b * 49;

    const __half* Qp = g ? Q1 : Q0;
    const __half* KV = g ? K1 : K0;
    __half* gO       = (g ? g_oy : g_ox) + (size_t)b * 49 * 256;

    const int r0 = R + gid, r1 = r0 + 8;
    const bool v0 = r0 < 49, v1 = r1 < 49;
    const int br0 = v0 ? r0 : 0, br1 = v1 ? r1 : 0;

    const int mi = lane >> 3, li = lane & 7;
    const uint32_t aRel = (uint32_t)((g * 2560 + (R + (mi & 1) * 8 + li) * 20 + (mi >> 1) * 4) * 4);
    uint32_t kRel[4];
#pragma unroll
    for (int np = 0; np < 4; np++)
        kRel[np] = (uint32_t)((g * 2560 + 1280 + ((2 * np + (mi >> 1)) * 8 + li) * 20 + (mi & 1) * 4) * 4);
    uint32_t vAddr[2];
#pragma unroll
    for (int np = 0; np < 2; np++)
        vAddr[np] = sb + (uint32_t)((AT_VT + g * 1152 + ((2 * np + (mi >> 1)) * 8 + li) * 36 + (mi & 1) * 4) * 4);

    fill_qk_g(sb, AT_ST0, g, Qp, KV, 0, tl);
    CP_COMMIT();

    for (int idx = t; idx < 2401; idx += 256) {
        int i = idx / 49, j = idx % 49;
        base[i * 50 + j] = nb[i] + nb[j] + mask[((size_t)wi * 49 + i) * 49 + j];
    }
    for (int idx = tl; idx < 1152; idx += 128) smw[AT_VT + g * 1152 + idx] = 0u;
    __syncthreads();

    __half* VtH = (__half*)(smw + AT_VT) + g * 2304;

    for (int h = 0; h < HEADS_; h++) {
        const int stw = (h & 1) ? AT_ST1 : AT_ST0;
        asm volatile("cp.async.wait_group 0;" ::: "memory");
        asm volatile("bar.sync %0, %1;" :: "r"(g + 1), "r"(128) : "memory");

        if (h < 7) {
            fill_qk_g(sb, (h & 1) ? AT_ST0 : AT_ST1, g, Qp, KV, h + 1, tl);
            CP_COMMIT();
        }

        const __half* Vb = KV + 256 + (size_t)h * 32;
        uint2 vreg[4];
#pragma unroll
        for (int i = 0; i < 4; i++) {
            int u = tl + i * 128;
            if (u < 392)
                vreg[i] = *(const uint2*)(Vb + (size_t)(u >> 3) * 768 + (u & 7) * 4);
        }

        const uint32_t stB = sb + (uint32_t)stw * 4;

        float cS[8][4];
#pragma unroll
        for (int i = 0; i < 8; i++)
#pragma unroll
            for (int j = 0; j < 4; j++) cS[i][j] = 0.f;
#pragma unroll
        for (int ks = 0; ks < 2; ks++) {
            unsigned a[4];
            ldm_x4(a, stB + aRel + ks * 32);
#pragma unroll
            for (int np = 0; np < 4; np++) {
                unsigned bf[4];
                ldm_x4(bf, stB + kRel[np] + ks * 32);
                unsigned b0[2] = { bf[0], bf[1] }, b1[2] = { bf[2], bf[3] };
                mma_f16(cS[2 * np], a, b0);
                mma_f16(cS[2 * np + 1], a, b1);
            }
        }

        const float* rpb = rpbH + h * 2452;
#pragma unroll
        for (int nt = 0; nt < 8; nt++) {
            int col = nt * 8 + tid4 * 2;
            bool jc0 = col < 49, jc1 = col < 48;
            float2 bs0 = *(const float2*)&base[br0 * 50 + col];
            float2 bs1 = *(const float2*)&base[br1 * 50 + col];
            float2 rp0 = *(const float2*)&rpb[br0 * 50 + col];
            float2 rp1 = *(const float2*)&rpb[br1 * 50 + col];
            cS[nt][0] = (v0 && jc0) ? cS[nt][0] + bs0.x + rp0.x : (v0 ? -1e30f : 0.f);
            cS[nt][1] = (v0 && jc1) ? cS[nt][1] + bs0.y + rp0.y : (v0 ? -1e30f : 0.f);
            cS[nt][2] = (v1 && jc0) ? cS[nt][2] + bs1.x + rp1.x : (v1 ? -1e30f : 0.f);
            cS[nt][3] = (v1 && jc1) ? cS[nt][3] + bs1.y + rp1.y : (v1 ? -1e30f : 0.f);
        }

        float m0 = -1e30f, m1 = -1e30f;
#pragma unroll
        for (int nt = 0; nt < 8; nt++) {
            m0 = fmaxf(m0, fmaxf(cS[nt][0], cS[nt][1]));
            m1 = fmaxf(m1, fmaxf(cS[nt][2], cS[nt][3]));
        }
#pragma unroll
        for (int o = 1; o <= 2; o <<= 1) {
            m0 = fmaxf(m0, __shfl_xor_sync(0xffffffffu, m0, o));
            m1 = fmaxf(m1, __shfl_xor_sync(0xffffffffu, m1, o));
        }
        float s0 = 0.f, s1 = 0.f;
#pragma unroll
        for (int nt = 0; nt < 8; nt++) {
            cS[nt][0] = __expf(cS[nt][0] - m0);
            cS[nt][1] = __expf(cS[nt][1] - m0);
            cS[nt][2] = __expf(cS[nt][2] - m1);
            cS[nt][3] = __expf(cS[nt][3] - m1);
            s0 += cS[nt][0] + cS[nt][1];
            s1 += cS[nt][2] + cS[nt][3];
        }
#pragma unroll
        for (int o = 1; o <= 2; o <<= 1) {
            s0 += __shfl_xor_sync(0xffffffffu, s0, o);
            s1 += __shfl_xor_sync(0xffffffffu, s1, o);
        }
        const float f0 = 1.f / s0, f1 = 1.f / s1;

        unsigned pA[4][4];
#pragma unroll
        for (int ks = 0; ks < 4; ks++) {
            pA[ks][0] = packh2(cS[2 * ks][0] * f0,     cS[2 * ks][1] * f0);
            pA[ks][1] = packh2(cS[2 * ks][2] * f1,     cS[2 * ks][3] * f1);
            pA[ks][2] = packh2(cS[2 * ks + 1][0] * f0, cS[2 * ks + 1][1] * f0);
            pA[ks][3] = packh2(cS[2 * ks + 1][2] * f1, cS[2 * ks + 1][3] * f1);
        }

#pragma unroll
        for (int i = 0; i < 4; i++) {
            int u = tl + i * 128;
            if (u < 392) {
                int j = u >> 3, d0 = (u & 7) * 4;
                __half2 p01 = *(__half2*)&vreg[i].x, p23 = *(__half2*)&vreg[i].y;
                VtH[(d0 + 0) * 72 + j] = p01.x;
                VtH[(d0 + 1) * 72 + j] = p01.y;
                VtH[(d0 + 2) * 72 + j] = p23.x;
                VtH[(d0 + 3) * 72 + j] = p23.y;
            }
        }
        asm volatile("bar.sync %0, %1;" :: "r"(g + 1), "r"(128) : "memory");

        float c2[4][4];
#pragma unroll
        for (int i = 0; i < 4; i++)
#pragma unroll
            for (int j = 0; j < 4; j++) c2[i][j] = 0.f;
#pragma unroll
        for (int ks = 0; ks < 4; ks++) {
#pragma unroll
            for (int np = 0; np < 2; np++) {
                unsigned bf[4];
                ldm_x4(bf, vAddr[np] + ks * 32);
                unsigned b0[2] = { bf[0], bf[1] }, b1[2] = { bf[2], bf[3] };
                mma_f16(c2[2 * np], pA[ks], b0);
                mma_f16(c2[2 * np + 1], pA[ks], b1);
            }
        }

        __half* gOb = gO + h * 32;
#pragma unroll
        for (int nt = 0; nt < 4; nt++) {
            int col = nt * 8 + tid4 * 2;
            if (v0) *(unsigned*)&gOb[(size_t)r0 * 256 + col] = packh2(c2[nt][0], c2[nt][1]);
            if (v1) *(unsigned*)&gOb[(size_t)r1 * 256 + col] = packh2(c2[nt][2], c2[nt][3]);
        }
    }
}

// ---------------- nuclei passthrough ----------------
__global__ void copy_nuc(const float* __restrict__ in, float* __restrict__ out, int n4)
{
    int i = blockIdx.x * 256 + threadIdx.x;
    if (i < n4) ((float4*)out)[i] = ((const float4*)in)[i];
}

// ---------------- launch ----------------
extern "C" void kernel_launch(void* const* d_in, const int* in_sizes, int n_in,
                              void* d_out, int out_size)
{
    const float* x        = (const float*)d_in[0];
    const float* y        = (const float*)d_in[1];
    const float* nuc      = (const float*)d_in[2];
    const float* mask     = (const float*)d_in[3];
    const float* rpbt     = (const float*)d_in[4];
    const float* qkv_w    = (const float*)d_in[5];
    const float* qkv_b    = (const float*)d_in[6];
    const float* qkv_y_w  = (const float*)d_in[7];
    const float* qkv_y_b  = (const float*)d_in[8];
    const float* proj_qx_w= (const float*)d_in[9];
    const float* proj_qx_b= (const float*)d_in[10];
    const float* proj_qy_w= (const float*)d_in[11];
    const float* proj_qy_b= (const float*)d_in[12];
    const float* proj_w   = (const float*)d_in[13];
    const float* proj_b   = (const float*)d_in[14];
    const float* proj_y_w = (const float*)d_in[15];
    const float* proj_y_b = (const float*)d_in[16];
    const int*   rpi      = (const int*)d_in[17];
    float* out = (float*)d_out;

    __half *xbuf, *ybuf, *ox, *oy, *wx, *wy, *pw, *py;
    float *bx, *by, *rpbH;
    cudaGetSymbolAddress((void**)&xbuf, g_xbuf);
    cudaGetSymbolAddress((void**)&ybuf, g_ybuf);
    cudaGetSymbolAddress((void**)&ox,   g_ox);
    cudaGetSymbolAddress((void**)&oy,   g_oy);
    cudaGetSymbolAddress((void**)&wx,   g_wx);
    cudaGetSymbolAddress((void**)&wy,   g_wy);
    cudaGetSymbolAddress((void**)&pw,   g_pw);
    cudaGetSymbolAddress((void**)&py,   g_py);
    cudaGetSymbolAddress((void**)&bx,   g_bx);
    cudaGetSymbolAddress((void**)&by,   g_by);
    cudaGetSymbolAddress((void**)&rpbH, g_rpbH);

    cudaFuncSetAttribute(attn_kernel, cudaFuncAttributeMaxDynamicSharedMemorySize,
                         ATTN_SMEM_BYTES);
    cudaFuncSetAttribute((const void*)gemm_h<0>, cudaFuncAttributeMaxDynamicSharedMemorySize,
                         GEMM_SMEM_BYTES);
    cudaFuncSetAttribute((const void*)gemm_h<1>, cudaFuncAttributeMaxDynamicSharedMemorySize,
                         GEMM_SMEM_BYTES);

    // prep: one launch
    prep_all<<<768, 256>>>(qkv_w, qkv_b, proj_qx_w, proj_qx_b,
                           qkv_y_w, qkv_y_b, proj_qy_w, proj_qy_b,
                           proj_w, proj_y_w, rpbt, rpi,
                           wx, bx, wy, by, pw, py, rpbH);

    const int mtiles = M_ROWS / 128;  // 1568

    // input projections (A fp32 -> C fp16), both streams
    gemm_h<0><<<dim3(6, mtiles, 2), 128, GEMM_SMEM_BYTES>>>(
        x, wx, bx, xbuf, y, wy, by, ybuf, 768);

    // attention (both paths, decoupled pipelines)
    attn_kernel<<<B_B, 256, ATTN_SMEM_BYTES>>>(nuc, mask, rpbH);

    // output projections (A fp16 -> C fp32), both
    gemm_h<1><<<dim3(2, mtiles, 2), 128, GEMM_SMEM_BYTES>>>(
        ox, pw, proj_b, out, oy, py, proj_y_b, out + (size_t)M_ROWS * 256, 256);

    copy_nuc<<<(M_ROWS / 4 + 255) / 256, 256>>>(nuc, out + 2 * (size_t)M_ROWS * 256,
                                                M_ROWS / 4);
}

// round 17
// speedup vs baseline: 1.0126x; 1.0126x over previous
#include <cuda_runtime.h>
#include <cuda_fp16.h>
#include <cstdint>

#define B_B 4096
#define HEADS_ 8
#define NW_ 64
#define Q_SCALE 0.17677669529663687f
#define M_ROWS (B_B * 49)              // 200704 = 1568 * 128

// ---------------- scratch ----------------
__device__ __align__(16) __half g_xbuf[(size_t)M_ROWS * 768];  // k|v|q fp16
__device__ __align__(16) __half g_ybuf[(size_t)M_ROWS * 768];
__device__ __align__(16) __half g_ox  [(size_t)M_ROWS * 256];
__device__ __align__(16) __half g_oy  [(size_t)M_ROWS * 256];
__device__ __align__(16) __half g_wx  [768 * 256];  // W^T [n][k] fp16
__device__ __align__(16) __half g_wy  [768 * 256];
__device__ __align__(16) __half g_pw  [256 * 256];
__device__ __align__(16) __half g_py  [256 * 256];
__device__ __align__(16) float  g_bx  [768];
__device__ __align__(16) float  g_by  [768];
__device__ __align__(16) float  g_rpbH[HEADS_ * 2452 + 64];    // +64 OOB pad

// ---------------- helpers ----------------
__device__ __forceinline__ uint32_t smem_u32(const void* p) {
    uint32_t a;
    asm("{ .reg .u64 t; cvta.to.shared.u64 t, %1; cvt.u32.u64 %0, t; }" : "=r"(a) : "l"(p));
    return a;
}
__device__ __forceinline__ unsigned packh2(float a, float b) {
    __half2 h = __floats2half2_rn(a, b);
    return *(unsigned*)&h;
}
__device__ __forceinline__ void mma_f16(float* c, const unsigned* a, const unsigned* b) {
    asm volatile(
        "mma.sync.aligned.m16n8k16.row.col.f32.f16.f16.f32 "
        "{%0,%1,%2,%3}, {%4,%5,%6,%7}, {%8,%9}, {%0,%1,%2,%3};\n"
        : "+f"(c[0]), "+f"(c[1]), "+f"(c[2]), "+f"(c[3])
        : "r"(a[0]), "r"(a[1]), "r"(a[2]), "r"(a[3]), "r"(b[0]), "r"(b[1]));
}
__device__ __forceinline__ void ldm_x4(unsigned* r, uint32_t addr) {
    asm volatile("ldmatrix.sync.aligned.m8n8.x4.shared.b16 {%0,%1,%2,%3}, [%4];"
        : "=r"(r[0]), "=r"(r[1]), "=r"(r[2]), "=r"(r[3]) : "r"(addr));
}
__device__ __forceinline__ void cpasync16(uint32_t dst, const void* src) {
    asm volatile("cp.async.cg.shared.global [%0], [%1], 16;" :: "r"(dst), "l"(src));
}
#define CP_COMMIT() asm volatile("cp.async.commit_group;" ::: "memory")
__device__ __forceinline__ void stcs_f2(float* p, float2 v) {
    asm volatile("st.global.cs.v2.f32 [%0], {%1, %2};" :: "l"(p), "f"(v.x), "f"(v.y) : "memory");
}
__device__ __forceinline__ void stcs_f4(float* p, float4 v) {
    asm volatile("st.global.cs.v4.f32 [%0], {%1, %2, %3, %4};"
                 :: "l"(p), "f"(v.x), "f"(v.y), "f"(v.z), "f"(v.w) : "memory");
}

// ---------------- prep: single kernel (incl. nuclei passthrough) ----------------
__global__ void prep_all(
    const float* __restrict__ qkv_w,   const float* __restrict__ qkv_b,
    const float* __restrict__ qxw,     const float* __restrict__ qxb,
    const float* __restrict__ qkv_y_w, const float* __restrict__ qkv_y_b,
    const float* __restrict__ qyw,     const float* __restrict__ qyb,
    const float* __restrict__ proj_w,  const float* __restrict__ proj_y_w,
    const float* __restrict__ rpbt,    const int* __restrict__ rpi,
    const float* __restrict__ nuc,     float* __restrict__ out_nuc,
    __half* __restrict__ wx, float* __restrict__ bxv,
    __half* __restrict__ wy, float* __restrict__ byv,
    __half* __restrict__ pw, __half* __restrict__ py,
    float* __restrict__ rpbH)
{
    int i = blockIdx.x * 256 + threadIdx.x;
    if (i < 768 * 256) {
        int n = i >> 8, k = i & 255;
        float vx = (n < 512) ? qkv_w[k * 512 + n]   : qxw[k * 256 + (n - 512)] * Q_SCALE;
        float vy = (n < 512) ? qkv_y_w[k * 512 + n] : qyw[k * 256 + (n - 512)] * Q_SCALE;
        wx[i] = __float2half_rn(vx);
        wy[i] = __float2half_rn(vy);
    }
    if (i < 768) {
        bxv[i] = (i < 512) ? qkv_b[i]   : qxb[i - 512] * Q_SCALE;
        byv[i] = (i < 512) ? qkv_y_b[i] : qyb[i - 512] * Q_SCALE;
    }
    if (i < 65536) {
        int n = i >> 8, k = i & 255;
        pw[i] = __float2half_rn(proj_w[k * 256 + n]);
        py[i] = __float2half_rn(proj_y_w[k * 256 + n]);
    }
    if (i < HEADS_ * 2401) {
        int h = i / 2401, ij = i % 2401;
        int r = ij / 49, j = ij % 49;
        rpbH[h * 2452 + r * 50 + j] = rpbt[rpi[ij] * 8 + h];
    }
    if (i < M_ROWS / 4) {   // nuclei passthrough (50176 float4)
        float4 v = ((const float4*)nuc)[i];
        stcs_f4(out_nuc + i * 4, v);
    }
}

// ---------------- fp16 mma GEMM w/ ldmatrix (R15 epilogue + .cs for fp32 out) ----
#define GH_AS0  0
#define GH_AS1  2560
#define GH_BS0  5120
#define GH_BS1  7680
#define GEMM_SMEM_BYTES (10240 * 4)

template<int AFP16>
__global__ __launch_bounds__(128) void gemm_h(
    const void* __restrict__ A0v, const __half* __restrict__ W0,
    const float* __restrict__ b0, void* __restrict__ C0v,
    const void* __restrict__ A1v, const __half* __restrict__ W1,
    const float* __restrict__ b1, void* __restrict__ C1v, int Ncol)
{
    extern __shared__ unsigned smg[];
    const uint32_t sb = smem_u32(smg);

    const void*  Av   = blockIdx.z ? A1v : A0v;
    const __half* W   = blockIdx.z ? W1 : W0;
    const float* bias = blockIdx.z ? b1 : b0;
    void*        Cv   = blockIdx.z ? C1v : C0v;

    const int t = threadIdx.x;
    const int warpId = t >> 5, lane = t & 31;
    const int gid = lane >> 2, tid4 = lane & 3;
    const int wm = (warpId & 1) * 64;
    const int wn = (warpId >> 1) * 64;
    const size_t tileM = (size_t)blockIdx.y * 128;
    const int tileN = blockIdx.x * 128;

    const int mi = lane >> 3, li = lane & 7;
    uint32_t aRel[4], bRel[4];
#pragma unroll
    for (int mt = 0; mt < 4; mt++)
        aRel[mt] = (uint32_t)(((wm + mt * 16 + (mi & 1) * 8 + li) * 20 + (mi >> 1) * 4) * 4);
#pragma unroll
    for (int np = 0; np < 4; np++)
        bRel[np] = (uint32_t)(((wn + (2 * np + (mi >> 1)) * 8 + li) * 20 + (mi & 1) * 4) * 4);

    float acc[4][8][4];
#pragma unroll
    for (int i = 0; i < 4; i++)
#pragma unroll
        for (int j = 0; j < 8; j++)
#pragma unroll
            for (int l = 0; l < 4; l++) acc[i][j][l] = 0.f;

#define GH_BFILL(stage, ch) do {                                                     \
    uint32_t bs_ = sb + ((stage) ? GH_BS1 : GH_BS0) * 4;                             \
    const __half* wsrc_ = W + (size_t)(tileN + t) * 256 + (ch) * 32;                 \
    _Pragma("unroll")                                                                \
    for (int cc = 0; cc < 4; cc++)                                                   \
        cpasync16(bs_ + (uint32_t)((t * 20 + cc * 4) * 4), wsrc_ + cc * 8);          \
} while (0)
#define GH_AFILL16(stage, ch) do {                                                   \
    uint32_t as_ = sb + ((stage) ? GH_AS1 : GH_AS0) * 4;                             \
    const __half* asrc_ = (const __half*)Av + (tileM + t) * 256 + (ch) * 32;         \
    _Pragma("unroll")                                                                \
    for (int cc = 0; cc < 4; cc++)                                                   \
        cpasync16(as_ + (uint32_t)((t * 20 + cc * 4) * 4), asrc_ + cc * 8);          \
} while (0)

    const int arow0 = t >> 3, aq = t & 7;
    const float* Af = (const float*)Av;
    float4 pa[8];

    if (AFP16) {
        GH_AFILL16(0, 0); GH_BFILL(0, 0); CP_COMMIT();
        GH_AFILL16(1, 1); GH_BFILL(1, 1); CP_COMMIT();
    } else {
#pragma unroll
        for (int i = 0; i < 8; i++)
            pa[i] = *(const float4*)(Af + (tileM + arow0 + i * 16) * 256 + aq * 4);
        GH_BFILL(0, 0); CP_COMMIT();
        GH_BFILL(1, 1); CP_COMMIT();
    }

    for (int c = 0; c < 8; c++) {
        const int s = c & 1;
        unsigned* As = smg + (s ? GH_AS1 : GH_AS0);
        const uint32_t aBase = sb + (s ? GH_AS1 : GH_AS0) * 4;
        const uint32_t bBase = sb + (s ? GH_BS1 : GH_BS0) * 4;

        if (!AFP16) {
#pragma unroll
            for (int i = 0; i < 8; i++) {
                uint2 u = { packh2(pa[i].x, pa[i].y), packh2(pa[i].z, pa[i].w) };
                *(uint2*)&As[(arow0 + i * 16) * 20 + aq * 2] = u;
            }
        }
        if (c < 7) asm volatile("cp.async.wait_group 1;" ::: "memory");
        else       asm volatile("cp.async.wait_group 0;" ::: "memory");
        __syncthreads();

        if (!AFP16 && c < 7) {
#pragma unroll
            for (int i = 0; i < 8; i++)
                pa[i] = *(const float4*)(Af + (tileM + arow0 + i * 16) * 256
                                         + (c + 1) * 32 + aq * 4);
        }

#pragma unroll
        for (int ks = 0; ks < 2; ks++) {
            unsigned a[4][4];
#pragma unroll
            for (int mt = 0; mt < 4; mt++)
                ldm_x4(a[mt], aBase + aRel[mt] + ks * 32);
            unsigned bf[4][4];
#pragma unroll
            for (int np = 0; np < 4; np++)
                ldm_x4(bf[np], bBase + bRel[np] + ks * 32);
#pragma unroll
            for (int nt = 0; nt < 8; nt++) {
                unsigned b2[2] = { bf[nt >> 1][(nt & 1) * 2], bf[nt >> 1][(nt & 1) * 2 + 1] };
#pragma unroll
                for (int mt = 0; mt < 4; mt++)
                    mma_f16(acc[mt][nt], a[mt], b2);
            }
        }
        __syncthreads();

        if (c < 6) {
            if (AFP16) GH_AFILL16(s, c + 2);
            GH_BFILL(s, c + 2);
            CP_COMMIT();
        }
    }

    // epilogue (R15 direct form; fp32 final output uses streaming stores)
#pragma unroll
    for (int mt = 0; mt < 4; mt++) {
        size_t row0 = tileM + wm + mt * 16 + gid;
#pragma unroll
        for (int nt = 0; nt < 8; nt++) {
            int col = tileN + wn + nt * 8 + tid4 * 2;
            float bb0 = bias[col], bb1 = bias[col + 1];
            float o0 = acc[mt][nt][0] + bb0, o1 = acc[mt][nt][1] + bb1;
            float o2 = acc[mt][nt][2] + bb0, o3 = acc[mt][nt][3] + bb1;
            if (AFP16) {
                float* C = (float*)Cv;
                float2 v0 = { o0, o1 }, v1 = { o2, o3 };
                stcs_f2(&C[row0 * Ncol + col], v0);
                stcs_f2(&C[(row0 + 8) * Ncol + col], v1);
            } else {
                __half* C = (__half*)Cv;
                *(unsigned*)&C[row0 * Ncol + col] = packh2(o0, o1);
                *(unsigned*)&C[(row0 + 8) * Ncol + col] = packh2(o2, o3);
            }
        }
    }
}

// ---------------- attention v4 (exact R15) ----------------
#define AT_ST0  0
#define AT_ST1  5120
#define AT_VT   10240
#define AT_BASE 12544
#define AT_TOT  (AT_BASE + 2452 + 64)
#define ATTN_SMEM_BYTES (AT_TOT * 4)     // 60,240 B

__device__ __forceinline__ void fill_qk_g(uint32_t sb, int stw, int g,
    const __half* Qp, const __half* Kp, int h, int tl)
{
    for (int u = tl; u < 392; u += 128) {
        int qk = u / 196, rem = u - qk * 196;
        int row = rem >> 2, cc = rem & 3;
        const __half* src = (qk ? Kp : Qp) + (size_t)h * 32 + row * 768 + cc * 8;
        uint32_t dstw = (uint32_t)(stw + g * 2560 + qk * 1280 + row * 20 + cc * 4);
        cpasync16(sb + dstw * 4, src);
    }
}

__global__ __launch_bounds__(256) void attn_kernel(
    const float* __restrict__ nuc, const float* __restrict__ mask,
    const float* __restrict__ rpbH)
{
    extern __shared__ unsigned smw[];
    const uint32_t sb = smem_u32(smw);
    float* base = (float*)(smw + AT_BASE);

    const int b = blockIdx.x;
    const __half* Q0 = g_ybuf + 512 + (size_t)b * 49 * 768;
    const __half* K0 = g_xbuf + (size_t)b * 49 * 768;
    const __half* Q1 = g_xbuf + 512 + (size_t)b * 49 * 768;
    const __half* K1 = g_ybuf + (size_t)b * 49 * 768;

    const int t = threadIdx.x;
    const int w = t >> 5, lane = t & 31;
    const int gid = lane >> 2, tid4 = lane & 3;
    const int g = w >> 2;
    const int R = (w & 3) * 16;
    const int tl = t & 127;
    const int wi = b & (NW_ - 1);
    const float* nb = nuc + (size_t)b * 49;

    const __half* Qp = g ? Q1 : Q0;
    const __half* KV = g ? K1 : K0;
    __half* gO       = (g ? g_oy : g_ox) + (size_t)b * 49 * 256;

    const int r0 = R + gid, r1 = r0 + 8;
    const bool v0 = r0 < 49, v1 = r1 < 49;
    const int br0 = v0 ? r0 : 0, br1 = v1 ? r1 : 0;

    const int mi = lane >> 3, li = lane & 7;
    const uint32_t aRel = (uint32_t)((g * 2560 + (R + (mi & 1) * 8 + li) * 20 + (mi >> 1) * 4) * 4);
    uint32_t kRel[4];
#pragma unroll
    for (int np = 0; np < 4; np++)
        kRel[np] = (uint32_t)((g * 2560 + 1280 + ((2 * np + (mi >> 1)) * 8 + li) * 20 + (mi & 1) * 4) * 4);
    uint32_t vAddr[2];
#pragma unroll
    for (int np = 0; np < 2; np++)
        vAddr[np] = sb + (uint32_t)((AT_VT + g * 1152 + ((2 * np + (mi >> 1)) * 8 + li) * 36 + (mi & 1) * 4) * 4);

    fill_qk_g(sb, AT_ST0, g, Qp, KV, 0, tl);
    CP_COMMIT();

    for (int idx = t; idx < 2401; idx += 256) {
        int i = idx / 49, j = idx % 49;
        base[i * 50 + j] = nb[i] + nb[j] + mask[((size_t)wi * 49 + i) * 49 + j];
    }
    for (int idx = tl; idx < 1152; idx += 128) smw[AT_VT + g * 1152 + idx] = 0u;
    __syncthreads();

    __half* VtH = (__half*)(smw + AT_VT) + g * 2304;

    for (int h = 0; h < HEADS_; h++) {
        const int stw = (h & 1) ? AT_ST1 : AT_ST0;
        asm volatile("cp.async.wait_group 0;" ::: "memory");
        asm volatile("bar.sync %0, %1;" :: "r"(g + 1), "r"(128) : "memory");

        if (h < 7) {
            fill_qk_g(sb, (h & 1) ? AT_ST0 : AT_ST1, g, Qp, KV, h + 1, tl);
            CP_COMMIT();
        }

        const __half* Vb = KV + 256 + (size_t)h * 32;
        uint2 vreg[4];
#pragma unroll
        for (int i = 0; i < 4; i++) {
            int u = tl + i * 128;
            if (u < 392)
                vreg[i] = *(const uint2*)(Vb + (size_t)(u >> 3) * 768 + (u & 7) * 4);
        }

        const uint32_t stB = sb + (uint32_t)stw * 4;

        float cS[8][4];
#pragma unroll
        for (int i = 0; i < 8; i++)
#pragma unroll
            for (int j = 0; j < 4; j++) cS[i][j] = 0.f;
#pragma unroll
        for (int ks = 0; ks < 2; ks++) {
            unsigned a[4];
            ldm_x4(a, stB + aRel + ks * 32);
#pragma unroll
            for (int np = 0; np < 4; np++) {
                unsigned bf[4];
                ldm_x4(bf, stB + kRel[np] + ks * 32);
                unsigned b0[2] = { bf[0], bf[1] }, b1[2] = { bf[2], bf[3] };
                mma_f16(cS[2 * np], a, b0);
                mma_f16(cS[2 * np + 1], a, b1);
            }
        }

        const float* rpb = rpbH + h * 2452;
#pragma unroll
        for (int nt = 0; nt < 8; nt++) {
            int col = nt * 8 + tid4 * 2;
            bool jc0 = col < 49, jc1 = col < 48;
            float2 bs0 = *(const float2*)&base[br0 * 50 + col];
            float2 bs1 = *(const float2*)&base[br1 * 50 + col];
            float2 rp0 = *(const float2*)&rpb[br0 * 50 + col];
            float2 rp1 = *(const float2*)&rpb[br1 * 50 + col];
            cS[nt][0] = (v0 && jc0) ? cS[nt][0] + bs0.x + rp0.x : (v0 ? -1e30f : 0.f);
            cS[nt][1] = (v0 && jc1) ? cS[nt][1] + bs0.y + rp0.y : (v0 ? -1e30f : 0.f);
            cS[nt][2] = (v1 && jc0) ? cS[nt][2] + bs1.x + rp1.x : (v1 ? -1e30f : 0.f);
            cS[nt][3] = (v1 && jc1) ? cS[nt][3] + bs1.y + rp1.y : (v1 ? -1e30f : 0.f);
        }

        float m0 = -1e30f, m1 = -1e30f;
#pragma unroll
        for (int nt = 0; nt < 8; nt++) {
            m0 = fmaxf(m0, fmaxf(cS[nt][0], cS[nt][1]));
            m1 = fmaxf(m1, fmaxf(cS[nt][2], cS[nt][3]));
        }
#pragma unroll
        for (int o = 1; o <= 2; o <<= 1) {
            m0 = fmaxf(m0, __shfl_xor_sync(0xffffffffu, m0, o));
            m1 = fmaxf(m1, __shfl_xor_sync(0xffffffffu, m1, o));
        }
        float s0 = 0.f, s1 = 0.f;
#pragma unroll
        for (int nt = 0; nt < 8; nt++) {
            cS[nt][0] = __expf(cS[nt][0] - m0);
            cS[nt][1] = __expf(cS[nt][1] - m0);
            cS[nt][2] = __expf(cS[nt][2] - m1);
            cS[nt][3] = __expf(cS[nt][3] - m1);
            s0 += cS[nt][0] + cS[nt][1];
            s1 += cS[nt][2] + cS[nt][3];
        }
#pragma unroll
        for (int o = 1; o <= 2; o <<= 1) {
            s0 += __shfl_xor_sync(0xffffffffu, s0, o);
            s1 += __shfl_xor_sync(0xffffffffu, s1, o);
        }
        const float f0 = 1.f / s0, f1 = 1.f / s1;

        unsigned pA[4][4];
#pragma unroll
        for (int ks = 0; ks < 4; ks++) {
            pA[ks][0] = packh2(cS[2 * ks][0] * f0,     cS[2 * ks][1] * f0);
            pA[ks][1] = packh2(cS[2 * ks][2] * f1,     cS[2 * ks][3] * f1);
            pA[ks][2] = packh2(cS[2 * ks + 1][0] * f0, cS[2 * ks + 1][1] * f0);
            pA[ks][3] = packh2(cS[2 * ks + 1][2] * f1, cS[2 * ks + 1][3] * f1);
        }

#pragma unroll
        for (int i = 0; i < 4; i++) {
            int u = tl + i * 128;
            if (u < 392) {
                int j = u >> 3, d0 = (u & 7) * 4;
                __half2 p01 = *(__half2*)&vreg[i].x, p23 = *(__half2*)&vreg[i].y;
                VtH[(d0 + 0) * 72 + j] = p01.x;
                VtH[(d0 + 1) * 72 + j] = p01.y;
                VtH[(d0 + 2) * 72 + j] = p23.x;
                VtH[(d0 + 3) * 72 + j] = p23.y;
            }
        }
        asm volatile("bar.sync %0, %1;" :: "r"(g + 1), "r"(128) : "memory");

        float c2[4][4];
#pragma unroll
        for (int i = 0; i < 4; i++)
#pragma unroll
            for (int j = 0; j < 4; j++) c2[i][j] = 0.f;
#pragma unroll
        for (int ks = 0; ks < 4; ks++) {
#pragma unroll
            for (int np = 0; np < 2; np++) {
                unsigned bf[4];
                ldm_x4(bf, vAddr[np] + ks * 32);
                unsigned b0[2] = { bf[0], bf[1] }, b1[2] = { bf[2], bf[3] };
                mma_f16(c2[2 * np], pA[ks], b0);
                mma_f16(c2[2 * np + 1], pA[ks], b1);
            }
        }

        __half* gOb = gO + h * 32;
#pragma unroll
        for (int nt = 0; nt < 4; nt++) {
            int col = nt * 8 + tid4 * 2;
            if (v0) *(unsigned*)&gOb[(size_t)r0 * 256 + col] = packh2(c2[nt][0], c2[nt][1]);
            if (v1) *(unsigned*)&gOb[(size_t)r1 * 256 + col] = packh2(c2[nt][2], c2[nt][3]);
        }
    }
}

// ---------------- launch ----------------
extern "C" void kernel_launch(void* const* d_in, const int* in_sizes, int n_in,
                              void* d_out, int out_size)
{
    const float* x        = (const float*)d_in[0];
    const float* y        = (const float*)d_in[1];
    const float* nuc      = (const float*)d_in[2];
    const float* mask     = (const float*)d_in[3];
    const float* rpbt     = (const float*)d_in[4];
    const float* qkv_w    = (const float*)d_in[5];
    const float* qkv_b    = (const float*)d_in[6];
    const float* qkv_y_w  = (const float*)d_in[7];
    const float* qkv_y_b  = (const float*)d_in[8];
    const float* proj_qx_w= (const float*)d_in[9];
    const float* proj_qx_b= (const float*)d_in[10];
    const float* proj_qy_w= (const float*)d_in[11];
    const float* proj_qy_b= (const float*)d_in[12];
    const float* proj_w   = (const float*)d_in[13];
    const float* proj_b   = (const float*)d_in[14];
    const float* proj_y_w = (const float*)d_in[15];
    const float* proj_y_b = (const float*)d_in[16];
    const int*   rpi      = (const int*)d_in[17];
    float* out = (float*)d_out;

    __half *xbuf, *ybuf, *ox, *oy, *wx, *wy, *pw, *py;
    float *bx, *by, *rpbH;
    cudaGetSymbolAddress((void**)&xbuf, g_xbuf);
    cudaGetSymbolAddress((void**)&ybuf, g_ybuf);
    cudaGetSymbolAddress((void**)&ox,   g_ox);
    cudaGetSymbolAddress((void**)&oy,   g_oy);
    cudaGetSymbolAddress((void**)&wx,   g_wx);
    cudaGetSymbolAddress((void**)&wy,   g_wy);
    cudaGetSymbolAddress((void**)&pw,   g_pw);
    cudaGetSymbolAddress((void**)&py,   g_py);
    cudaGetSymbolAddress((void**)&bx,   g_bx);
    cudaGetSymbolAddress((void**)&by,   g_by);
    cudaGetSymbolAddress((void**)&rpbH, g_rpbH);

    cudaFuncSetAttribute(attn_kernel, cudaFuncAttributeMaxDynamicSharedMemorySize,
                         ATTN_SMEM_BYTES);
    cudaFuncSetAttribute((const void*)gemm_h<0>, cudaFuncAttributeMaxDynamicSharedMemorySize,
                         GEMM_SMEM_BYTES);
    cudaFuncSetAttribute((const void*)gemm_h<1>, cudaFuncAttributeMaxDynamicSharedMemorySize,
                         GEMM_SMEM_BYTES);

    // prep (incl. nuclei passthrough): one launch
    prep_all<<<768, 256>>>(qkv_w, qkv_b, proj_qx_w, proj_qx_b,
                           qkv_y_w, qkv_y_b, proj_qy_w, proj_qy_b,
                           proj_w, proj_y_w, rpbt, rpi,
                           nuc, out + 2 * (size_t)M_ROWS * 256,
                           wx, bx, wy, by, pw, py, rpbH);

    const int mtiles = M_ROWS / 128;  // 1568

    // input projections (A fp32 -> C fp16), both streams
    gemm_h<0><<<dim3(6, mtiles, 2), 128, GEMM_SMEM_BYTES>>>(
        x, wx, bx, xbuf, y, wy, by, ybuf, 768);

    // attention (both paths, decoupled pipelines)
    attn_kernel<<<B_B, 256, ATTN_SMEM_BYTES>>>(nuc, mask, rpbH);

    // output projections (A fp16 -> C fp32 streaming), both
    gemm_h<1><<<dim3(2, mtiles, 2), 128, GEMM_SMEM_BYTES>>>(
        ox, pw, proj_b, out, oy, py, proj_y_b, out + (size_t)M_ROWS * 256, 256);
}